// round 1
// baseline (speedup 1.0000x reference)
#include <cuda_runtime.h>
#include <cuda_bf16.h>
#include <cstdint>

// Problem dims
#define NB   2048   // batch rows
#define ND   512    // input dim (K of first GEMM)
#define NH   64     // heads
#define NHID 2048   // hidden
#define KP   1536   // 3*ND: [x_hi*W_hi | x_hi*W_lo | x_lo*W_hi]

// Tiling
#define BM 128
#define BN 128
#define BK 64
#define LDA 72     // padded smem stride for A (bf16 elems)
#define LDB 136    // padded smem stride for B (bf16 elems)

// Scratch for bf16 hi/lo splits (device globals: allocation-free per harness rules)
__device__ __nv_bfloat16 g_Whi[(size_t)NH * ND * NHID];
__device__ __nv_bfloat16 g_Wlo[(size_t)NH * ND * NHID];
__device__ __nv_bfloat16 g_Xhi[(size_t)NB * ND];
__device__ __nv_bfloat16 g_Xlo[(size_t)NB * ND];

__device__ __forceinline__ uint32_t smem_u32(const void* p) {
    return (uint32_t)__cvta_generic_to_shared(p);
}

// ---------------------------------------------------------------------------
// Split fp32 -> bf16 hi + bf16 lo (lo = round(x - float(hi)))
// ---------------------------------------------------------------------------
__global__ void convert_w_kernel(const float* __restrict__ W1) {
    size_t i = (size_t)blockIdx.x * blockDim.x + threadIdx.x;
    const size_t n4 = (size_t)NH * ND * NHID / 4;
    if (i >= n4) return;
    float4 v = ((const float4*)W1)[i];
    __nv_bfloat16 h0 = __float2bfloat16(v.x);
    __nv_bfloat16 h1 = __float2bfloat16(v.y);
    __nv_bfloat16 h2 = __float2bfloat16(v.z);
    __nv_bfloat16 h3 = __float2bfloat16(v.w);
    __nv_bfloat16 l0 = __float2bfloat16(v.x - __bfloat162float(h0));
    __nv_bfloat16 l1 = __float2bfloat16(v.y - __bfloat162float(h1));
    __nv_bfloat16 l2 = __float2bfloat16(v.z - __bfloat162float(h2));
    __nv_bfloat16 l3 = __float2bfloat16(v.w - __bfloat162float(h3));
    __nv_bfloat162* dhi = (__nv_bfloat162*)g_Whi;
    __nv_bfloat162* dlo = (__nv_bfloat162*)g_Wlo;
    dhi[2 * i]     = __halves2bfloat162(h0, h1);
    dhi[2 * i + 1] = __halves2bfloat162(h2, h3);
    dlo[2 * i]     = __halves2bfloat162(l0, l1);
    dlo[2 * i + 1] = __halves2bfloat162(l2, l3);
}

__global__ void convert_x_kernel(const float* __restrict__ X) {
    size_t i = (size_t)blockIdx.x * blockDim.x + threadIdx.x;
    const size_t n4 = (size_t)NB * ND / 4;
    if (i >= n4) return;
    float4 v = ((const float4*)X)[i];
    __nv_bfloat16 h0 = __float2bfloat16(v.x);
    __nv_bfloat16 h1 = __float2bfloat16(v.y);
    __nv_bfloat16 h2 = __float2bfloat16(v.z);
    __nv_bfloat16 h3 = __float2bfloat16(v.w);
    __nv_bfloat16 l0 = __float2bfloat16(v.x - __bfloat162float(h0));
    __nv_bfloat16 l1 = __float2bfloat16(v.y - __bfloat162float(h1));
    __nv_bfloat16 l2 = __float2bfloat16(v.z - __bfloat162float(h2));
    __nv_bfloat16 l3 = __float2bfloat16(v.w - __bfloat162float(h3));
    __nv_bfloat162* dhi = (__nv_bfloat162*)g_Xhi;
    __nv_bfloat162* dlo = (__nv_bfloat162*)g_Xlo;
    dhi[2 * i]     = __halves2bfloat162(h0, h1);
    dhi[2 * i + 1] = __halves2bfloat162(h2, h3);
    dlo[2 * i]     = __halves2bfloat162(l0, l1);
    dlo[2 * i + 1] = __halves2bfloat162(l2, l3);
}

// ---------------------------------------------------------------------------
// Fused multi-head MLP: per CTA = (m-tile of 128 rows, head h).
// Loop n-tiles of HID; inner K'=1536 bf16x3 GEMM via mma.sync; epilogue fuses
// bias + leaky_relu + dot with W2 so the [B,H,HID] intermediate never hits mem.
// ---------------------------------------------------------------------------
__global__ void __launch_bounds__(256)
mhmlp_main_kernel(const float* __restrict__ b1,
                  const float* __restrict__ W2,
                  const float* __restrict__ b2,
                  float* __restrict__ out)
{
    __shared__ __nv_bfloat16 sA[BM * LDA];
    __shared__ __nv_bfloat16 sB[BK * LDB];
    __shared__ float rowacc[BM];

    const int tid  = threadIdx.x;
    const int lane = tid & 31;
    const int wid  = tid >> 5;          // 8 warps
    const int wm   = wid >> 1;          // 0..3 (M)
    const int wn   = wid & 1;           // 0..1 (N)

    const int mt = blockIdx.x;          // 16 m-tiles (fast dim -> L2 head reuse)
    const int h  = blockIdx.y;          // 64 heads
    const int m0 = mt * BM;

    const float* __restrict__ b1h = b1 + (size_t)h * NHID;
    const float* __restrict__ W2h = W2 + (size_t)h * NHID;

    float acc4[4] = {0.f, 0.f, 0.f, 0.f};

    for (int nt = 0; nt < NHID / BN; ++nt) {
        float c[2][8][4];
        #pragma unroll
        for (int mi = 0; mi < 2; ++mi)
            #pragma unroll
            for (int ni = 0; ni < 8; ++ni)
                #pragma unroll
                for (int e = 0; e < 4; ++e) c[mi][ni][e] = 0.f;

        for (int kt = 0; kt < KP / BK; ++kt) {
            const int region = kt >> 3;           // 0,1,2 (8 BK-tiles per 512)
            const int kin    = (kt & 7) * BK;     // 0..448 within ND
            const __nv_bfloat16* __restrict__ Asrc = (region < 2)  ? g_Xhi : g_Xlo;
            const __nv_bfloat16* __restrict__ Bsrc = (region == 1) ? g_Wlo : g_Whi;

            // Stage A: BM x BK (row-major, K contiguous), 16B vectors
            #pragma unroll
            for (int i = tid; i < BM * BK / 8; i += 256) {
                int r  = i >> 3;
                int cv = i & 7;
                uint4 v = *(const uint4*)(Asrc + (size_t)(m0 + r) * ND + kin + cv * 8);
                *(uint4*)(&sA[r * LDA + cv * 8]) = v;
            }
            // Stage B: BK x BN (row-major, N contiguous)
            #pragma unroll
            for (int i = tid; i < BK * BN / 8; i += 256) {
                int r  = i >> 4;
                int cv = i & 15;
                uint4 v = *(const uint4*)(Bsrc + ((size_t)h * ND + kin + r) * NHID
                                          + nt * BN + cv * 8);
                *(uint4*)(&sB[r * LDB + cv * 8]) = v;
            }
            __syncthreads();

            #pragma unroll
            for (int ks = 0; ks < BK / 16; ++ks) {
                uint32_t a[2][4];
                #pragma unroll
                for (int mi = 0; mi < 2; ++mi) {
                    int row = wm * 32 + mi * 16 + (lane & 15);
                    int col = ks * 16 + (lane >> 4) * 8;
                    uint32_t ad = smem_u32(&sA[row * LDA + col]);
                    asm volatile(
                        "ldmatrix.sync.aligned.m8n8.x4.shared.b16 {%0,%1,%2,%3}, [%4];"
                        : "=r"(a[mi][0]), "=r"(a[mi][1]), "=r"(a[mi][2]), "=r"(a[mi][3])
                        : "r"(ad));
                }
                uint32_t bfr[8][2];
                #pragma unroll
                for (int np = 0; np < 4; ++np) {   // pairs of n8 tiles
                    int row = ks * 16 + (lane & 15);
                    int col = wn * 64 + np * 16 + (lane >> 4) * 8;
                    uint32_t ad = smem_u32(&sB[row * LDB + col]);
                    uint32_t r0, r1, r2, r3;
                    asm volatile(
                        "ldmatrix.sync.aligned.m8n8.x4.trans.shared.b16 {%0,%1,%2,%3}, [%4];"
                        : "=r"(r0), "=r"(r1), "=r"(r2), "=r"(r3)
                        : "r"(ad));
                    bfr[2 * np][0] = r0;  bfr[2 * np][1] = r1;
                    bfr[2 * np + 1][0] = r2;  bfr[2 * np + 1][1] = r3;
                }
                #pragma unroll
                for (int mi = 0; mi < 2; ++mi)
                    #pragma unroll
                    for (int ni = 0; ni < 8; ++ni) {
                        asm volatile(
                            "mma.sync.aligned.m16n8k16.row.col.f32.bf16.bf16.f32 "
                            "{%0,%1,%2,%3}, {%4,%5,%6,%7}, {%8,%9}, {%0,%1,%2,%3};"
                            : "+f"(c[mi][ni][0]), "+f"(c[mi][ni][1]),
                              "+f"(c[mi][ni][2]), "+f"(c[mi][ni][3])
                            : "r"(a[mi][0]), "r"(a[mi][1]), "r"(a[mi][2]), "r"(a[mi][3]),
                              "r"(bfr[ni][0]), "r"(bfr[ni][1]));
                    }
            }
            __syncthreads();
        }

        // Epilogue for this n-tile: bias + leaky + dot with W2, row accumulate
        #pragma unroll
        for (int mi = 0; mi < 2; ++mi)
            #pragma unroll
            for (int ni = 0; ni < 8; ++ni)
                #pragma unroll
                for (int e = 0; e < 4; ++e) {
                    int ncol = wn * 64 + ni * 8 + (lane & 3) * 2 + (e & 1);
                    int ng   = nt * BN + ncol;
                    float p = c[mi][ni][e] + __ldg(&b1h[ng]);
                    float v = (p >= 0.f) ? p : 0.01f * p;
                    acc4[mi * 2 + (e >> 1)] += v * __ldg(&W2h[ng]);
                }
    }

    // Reduce within lane quads (lanes sharing a row differ only in lane&3)
    #pragma unroll
    for (int off = 1; off <= 2; off <<= 1)
        #pragma unroll
        for (int j = 0; j < 4; ++j)
            acc4[j] += __shfl_xor_sync(0xffffffffu, acc4[j], off);

    __syncthreads();                 // done with sA/sB reads
    if (tid < BM) rowacc[tid] = 0.f;
    __syncthreads();
    if ((lane & 3) == 0) {
        int rbase = wm * 32 + (lane >> 2);
        atomicAdd(&rowacc[rbase +  0], acc4[0]);
        atomicAdd(&rowacc[rbase +  8], acc4[1]);
        atomicAdd(&rowacc[rbase + 16], acc4[2]);
        atomicAdd(&rowacc[rbase + 24], acc4[3]);
    }
    __syncthreads();
    if (tid < BM) {
        float v = rowacc[tid] + __ldg(&b2[h]);
        out[(size_t)(m0 + tid) * NH + h] = (v >= 0.f) ? v : 0.01f * v;
    }
}

// ---------------------------------------------------------------------------
// Launch
// ---------------------------------------------------------------------------
extern "C" void kernel_launch(void* const* d_in, const int* in_sizes, int n_in,
                              void* d_out, int out_size) {
    const float* x  = (const float*)d_in[0];   // [2048, 512]
    const float* W1 = (const float*)d_in[1];   // [64, 512, 2048]
    const float* b1 = (const float*)d_in[2];   // [64, 2048]
    const float* W2 = (const float*)d_in[3];   // [64, 2048]
    const float* b2 = (const float*)d_in[4];   // [64]
    float* out = (float*)d_out;                // [2048, 64]

    (void)in_sizes; (void)n_in; (void)out_size;

    {   // split W1 -> bf16 hi/lo
        size_t n4 = (size_t)NH * ND * NHID / 4;
        int blocks = (int)((n4 + 255) / 256);
        convert_w_kernel<<<blocks, 256>>>(W1);
    }
    {   // split x -> bf16 hi/lo
        size_t n4 = (size_t)NB * ND / 4;
        int blocks = (int)((n4 + 255) / 256);
        convert_x_kernel<<<blocks, 256>>>(x);
    }

    dim3 grid(NB / BM, NH);   // m-tile fast, head slow -> W1[h] stays in L2
    mhmlp_main_kernel<<<grid, 256>>>(b1, W2, b2, out);
}

// round 3
// speedup vs baseline: 2.4259x; 2.4259x over previous
#include <cuda_runtime.h>
#include <cuda_fp16.h>
#include <cstdint>

// Problem dims
#define NB   2048
#define ND   512
#define NH   64
#define NHID 2048

// Tiling
#define BM   256
#define BN   128
#define BK   64
#define NTHREADS 512
#define NSTAGE 3
#define NCHUNK 128        // 16 n-tiles * 8 k-tiles

// smem layout (half elems, padded rows)
#define LDA  72           // 64 + 8 pad -> 144B row stride
#define LDB  136          // 128 + 8 pad -> 272B
#define ASTAGE (BM * LDA * 2)             // 36864 B
#define BSTAGE (BK * LDB * 2)             // 17408 B
#define STAGE  (ASTAGE + BSTAGE)          // 54272 B
#define OFF_ROWACC (NSTAGE * STAGE)       // 162816
#define SMEM_DYN  (OFF_ROWACC + BM * 4 + 256)

// fp16 copies (device globals; allocation-free per harness rules)
__device__ __half g_Wh[(size_t)NH * ND * NHID];   // [H][D][HID], n contiguous
__device__ __half g_Xh[(size_t)NB * ND];          // [B][D], k contiguous

__device__ __forceinline__ uint32_t smem_u32(const void* p) {
    return (uint32_t)__cvta_generic_to_shared(p);
}
__device__ __forceinline__ void cp16(uint32_t dst, const void* src) {
    asm volatile("cp.async.cg.shared.global [%0], [%1], 16;" :: "r"(dst), "l"(src));
}
__device__ __forceinline__ float lrelu(float v) {
    return (v >= 0.f) ? v : 0.01f * v;
}

// ---------------------------------------------------------------------------
// fp32 -> fp16 converts (elementwise, vectorized)
// ---------------------------------------------------------------------------
__global__ void convert_w_kernel(const float* __restrict__ W1) {
    size_t i = (size_t)blockIdx.x * blockDim.x + threadIdx.x;
    const size_t n4 = (size_t)NH * ND * NHID / 4;
    if (i >= n4) return;
    float4 v = ((const float4*)W1)[i];
    __half2* d = (__half2*)g_Wh;
    d[2 * i]     = __floats2half2_rn(v.x, v.y);
    d[2 * i + 1] = __floats2half2_rn(v.z, v.w);
}
__global__ void convert_x_kernel(const float* __restrict__ X) {
    size_t i = (size_t)blockIdx.x * blockDim.x + threadIdx.x;
    const size_t n4 = (size_t)NB * ND / 4;
    if (i >= n4) return;
    float4 v = ((const float4*)X)[i];
    __half2* d = (__half2*)g_Xh;
    d[2 * i]     = __floats2half2_rn(v.x, v.y);
    d[2 * i + 1] = __floats2half2_rn(v.z, v.w);
}

// ---------------------------------------------------------------------------
// Fused multi-head MLP, fp16 mma.sync, 3-stage cp.async pipeline.
// CTA = (256-row m-tile, head). Warp grid 4(M)x4(N): warp tile 64x32.
// Epilogue per n-tile fuses bias + leaky + dot(W2) into per-row scalars.
// ---------------------------------------------------------------------------
__global__ void __launch_bounds__(NTHREADS, 1)
mhmlp_main_kernel(const float* __restrict__ b1, const float* __restrict__ W2,
                  const float* __restrict__ b2, float* __restrict__ out)
{
    extern __shared__ char smem[];
    const uint32_t sbase = smem_u32(smem);
    float* rowacc = (float*)(smem + OFF_ROWACC);

    const int tid  = threadIdx.x;
    const int lane = tid & 31;
    const int wid  = tid >> 5;
    const int wm   = wid >> 2;     // 0..3 : M (64 rows)
    const int wn   = wid & 3;      // 0..3 : N (32 cols)

    const int mt = blockIdx.x;     // 8 (fast dim -> head weights hot in L2)
    const int h  = blockIdx.y;     // 64
    const int m0 = mt * BM;

    if (tid < BM) rowacc[tid] = 0.f;

    const __half* __restrict__ Xh = g_Xh;
    const __half* __restrict__ Wh = g_Wh + (size_t)h * ND * NHID;
    const float* __restrict__ b1h = b1 + (size_t)h * NHID;
    const float* __restrict__ W2h = W2 + (size_t)h * NHID;

    // ---- stage one (nt, kt) chunk into pipeline buffer s ----
    auto stage = [&](int s, int cc) {
        const int nt = cc >> 3;
        const int kt = cc & 7;
        const uint32_t sb = sbase + s * STAGE;
        #pragma unroll
        for (int i = 0; i < 4; i++) {                  // A: 2048 16B segs
            int t = tid + i * NTHREADS;
            int r = t >> 3, seg = t & 7;
            const void* src = Xh + (size_t)(m0 + r) * ND + kt * BK + seg * 8;
            cp16(sb + r * (LDA * 2) + seg * 16, src);
        }
        #pragma unroll
        for (int i = 0; i < 2; i++) {                  // B: 1024 16B segs
            int t = tid + i * NTHREADS;
            int r = t >> 4, seg = t & 15;
            const void* src = Wh + (size_t)(kt * BK + r) * NHID + nt * BN + seg * 8;
            cp16(sb + ASTAGE + r * (LDB * 2) + seg * 16, src);
        }
    };

    float c[4][4][4];
    #pragma unroll
    for (int mi = 0; mi < 4; mi++)
        #pragma unroll
        for (int ni = 0; ni < 4; ni++)
            #pragma unroll
            for (int e = 0; e < 4; e++) c[mi][ni][e] = 0.f;
    float accrow[8] = {0.f,0.f,0.f,0.f,0.f,0.f,0.f,0.f};

    stage(0, 0); asm volatile("cp.async.commit_group;" ::: "memory");
    stage(1, 1); asm volatile("cp.async.commit_group;" ::: "memory");

    for (int cc = 0; cc < NCHUNK; ++cc) {
        if (cc + 2 < NCHUNK) stage((cc + 2) % NSTAGE, cc + 2);
        asm volatile("cp.async.commit_group;" ::: "memory");
        asm volatile("cp.async.wait_group %0;" :: "n"(NSTAGE - 1) : "memory");
        __syncthreads();

        const uint32_t aB = sbase + (cc % NSTAGE) * STAGE;
        const uint32_t bB = aB + ASTAGE;

        #pragma unroll
        for (int ks = 0; ks < 4; ks++) {
            uint32_t a[4][4];
            #pragma unroll
            for (int mi = 0; mi < 4; mi++) {
                uint32_t ad = aB + (wm * 64 + mi * 16 + (lane & 15)) * (LDA * 2)
                            + (ks * 16 + (lane >> 4) * 8) * 2;
                asm volatile(
                    "ldmatrix.sync.aligned.m8n8.x4.shared.b16 {%0,%1,%2,%3}, [%4];"
                    : "=r"(a[mi][0]), "=r"(a[mi][1]), "=r"(a[mi][2]), "=r"(a[mi][3])
                    : "r"(ad));
            }
            uint32_t bf[4][2];
            #pragma unroll
            for (int np = 0; np < 2; np++) {
                uint32_t ad = bB + (ks * 16 + (lane & 15)) * (LDB * 2)
                            + (wn * 32 + np * 16 + (lane >> 4) * 8) * 2;
                uint32_t r0, r1, r2, r3;
                asm volatile(
                    "ldmatrix.sync.aligned.m8n8.x4.trans.shared.b16 {%0,%1,%2,%3}, [%4];"
                    : "=r"(r0), "=r"(r1), "=r"(r2), "=r"(r3) : "r"(ad));
                bf[2 * np][0] = r0;     bf[2 * np][1] = r1;
                bf[2 * np + 1][0] = r2; bf[2 * np + 1][1] = r3;
            }
            #pragma unroll
            for (int mi = 0; mi < 4; mi++)
                #pragma unroll
                for (int ni = 0; ni < 4; ni++) {
                    asm volatile(
                        "mma.sync.aligned.m16n8k16.row.col.f32.f16.f16.f32 "
                        "{%0,%1,%2,%3}, {%4,%5,%6,%7}, {%8,%9}, {%0,%1,%2,%3};"
                        : "+f"(c[mi][ni][0]), "+f"(c[mi][ni][1]),
                          "+f"(c[mi][ni][2]), "+f"(c[mi][ni][3])
                        : "r"(a[mi][0]), "r"(a[mi][1]), "r"(a[mi][2]), "r"(a[mi][3]),
                          "r"(bf[ni][0]), "r"(bf[ni][1]));
                }
        }
        __syncthreads();

        if ((cc & 7) == 7) {   // end of K for this n-tile: fused epilogue
            const int nt = cc >> 3;
            #pragma unroll
            for (int mi = 0; mi < 4; mi++)
                #pragma unroll
                for (int ni = 0; ni < 4; ni++)
                    #pragma unroll
                    for (int e = 0; e < 4; e++) {
                        int col = nt * BN + wn * 32 + ni * 8 + (lane & 3) * 2 + (e & 1);
                        float p = c[mi][ni][e] + __ldg(&b1h[col]);
                        accrow[mi * 2 + (e >> 1)] = fmaf(lrelu(p), __ldg(&W2h[col]),
                                                         accrow[mi * 2 + (e >> 1)]);
                        c[mi][ni][e] = 0.f;
                    }
        }
    }

    // reduce the 4 lanes sharing each row, then across wn warps via smem
    #pragma unroll
    for (int off = 1; off <= 2; off <<= 1)
        #pragma unroll
        for (int j = 0; j < 8; j++)
            accrow[j] += __shfl_xor_sync(0xffffffffu, accrow[j], off);

    if ((lane & 3) == 0) {
        #pragma unroll
        for (int mi = 0; mi < 4; mi++)
            #pragma unroll
            for (int e2 = 0; e2 < 2; e2++) {
                int row = wm * 64 + mi * 16 + e2 * 8 + (lane >> 2);
                atomicAdd(&rowacc[row], accrow[mi * 2 + e2]);
            }
    }
    __syncthreads();
    if (tid < BM) {
        float v = rowacc[tid] + __ldg(&b2[h]);
        out[(size_t)(m0 + tid) * NH + h] = lrelu(v);
    }
}

// ---------------------------------------------------------------------------
extern "C" void kernel_launch(void* const* d_in, const int* in_sizes, int n_in,
                              void* d_out, int out_size) {
    const float* x  = (const float*)d_in[0];   // [2048, 512]
    const float* W1 = (const float*)d_in[1];   // [64, 512, 2048]
    const float* b1 = (const float*)d_in[2];   // [64, 2048]
    const float* W2 = (const float*)d_in[3];   // [64, 2048]
    const float* b2 = (const float*)d_in[4];   // [64]
    float* out = (float*)d_out;                // [2048, 64]
    (void)in_sizes; (void)n_in; (void)out_size;

    cudaFuncSetAttribute(mhmlp_main_kernel,
                         cudaFuncAttributeMaxDynamicSharedMemorySize, SMEM_DYN);

    {
        size_t n4 = (size_t)NH * ND * NHID / 4;
        convert_w_kernel<<<(int)((n4 + 255) / 256), 256>>>(W1);
    }
    {
        size_t n4 = (size_t)NB * ND / 4;
        convert_x_kernel<<<(int)((n4 + 255) / 256), 256>>>(x);
    }

    dim3 grid(NB / BM, NH);
    mhmlp_main_kernel<<<grid, NTHREADS, SMEM_DYN>>>(b1, W2, b2, out);
}